// round 1
// baseline (speedup 1.0000x reference)
#include <cuda_runtime.h>
#include <cuda_bf16.h>

#define N_COARSE 100000
#define M_FINE   400000
#define C_IN     32
#define C_HID    64
#define C_OUT    32
#define K3       27

// ---------------- scratch (static device globals; no allocation) ----------------
__device__ float g_bufA[N_COARSE * C_HID];   // 25.6 MB
__device__ float g_bufB[N_COARSE * C_HID];   // 25.6 MB
__device__ float g_t[M_FINE * C_HID];        // 102.4 MB

// ---------------- packed f32x2 helpers ----------------
__device__ __forceinline__ unsigned long long ffma2(unsigned long long a,
                                                    unsigned long long b,
                                                    unsigned long long c) {
    unsigned long long d;
    asm("fma.rn.f32x2 %0, %1, %2, %3;" : "=l"(d) : "l"(a), "l"(b), "l"(c));
    return d;
}
__device__ __forceinline__ unsigned long long pack2(float lo, float hi) {
    unsigned long long r;
    asm("mov.b64 %0, {%1, %2};" : "=l"(r) : "f"(lo), "f"(hi));
    return r;
}
__device__ __forceinline__ float2 unpack2(unsigned long long v) {
    float2 r;
    asm("mov.b64 {%0, %1}, %2;" : "=f"(r.x), "=f"(r.y) : "l"(v));
    return r;
}

// ---------------- sparse 3x3x3 conv: out[N,64] = relu(sum_k gather(x,nbr[:,k]) @ W[k] + b) ----------------
// Block: 32 voxels, 256 threads. Thread computes 4 voxels x 2 couts, f32x2-packed.
template <int CIN>
__global__ void __launch_bounds__(256)
conv3_kernel(const float* __restrict__ x, const int* __restrict__ nbr,
             const float* __restrict__ W, const float* __restrict__ b,
             float* __restrict__ out) {
    constexpr int COUT = C_HID;           // 64
    constexpr int V = 32;
    __shared__ float sW[CIN * COUT];
    __shared__ float sx[V * CIN];
    __shared__ int   sidx[V * K3];

    const int tid = threadIdx.x;
    const int tx  = tid & 31;             // cout pair: couts {2tx, 2tx+1}
    const int ty  = tid >> 5;             // voxel group (4 voxels each)
    const int vb  = blockIdx.x * V;       // 3125 blocks exactly covers N

    // preload all 27 neighbor indices for this tile (coalesced)
    #pragma unroll
    for (int it = 0; it < (V * K3 + 255) / 256; ++it) {
        int i = it * 256 + tid;
        if (i < V * K3) sidx[i] = nbr[vb * K3 + i];
    }

    unsigned long long acc[4] = {0ull, 0ull, 0ull, 0ull};

    for (int k = 0; k < K3; ++k) {
        __syncthreads();  // prior compute done reading sx/sW
        // load W[k] into smem
        const float* Wk = W + k * CIN * COUT;
        #pragma unroll
        for (int it = 0; it < (CIN * COUT) / 1024; ++it) {
            int i = it * 1024 + tid * 4;
            *(float4*)(sW + i) = *(const float4*)(Wk + i);
        }
        // gather neighbor features into smem (sentinel index == N_COARSE -> zeros)
        #pragma unroll
        for (int it = 0; it < (V * CIN) / 1024; ++it) {
            int i = it * 1024 + tid * 4;
            int v = i / CIN;
            int c = i - v * CIN;
            int idx = sidx[v * K3 + k];
            float4 val = make_float4(0.f, 0.f, 0.f, 0.f);
            if (idx < N_COARSE) val = *(const float4*)(x + idx * CIN + c);
            *(float4*)(sx + i) = val;
        }
        __syncthreads();
        // compute
        #pragma unroll
        for (int c = 0; c < CIN; c += 4) {
            float xs[4][4];
            #pragma unroll
            for (int i = 0; i < 4; ++i) {
                float4 t4 = *(const float4*)(sx + (ty * 4 + i) * CIN + c);
                xs[i][0] = t4.x; xs[i][1] = t4.y; xs[i][2] = t4.z; xs[i][3] = t4.w;
            }
            #pragma unroll
            for (int cc = 0; cc < 4; ++cc) {
                float2 w = *(const float2*)(sW + (c + cc) * COUT + tx * 2);
                unsigned long long w2 = pack2(w.x, w.y);
                #pragma unroll
                for (int i = 0; i < 4; ++i)
                    acc[i] = ffma2(pack2(xs[i][cc], xs[i][cc]), w2, acc[i]);
            }
        }
    }

    float2 bv = *(const float2*)(b + tx * 2);
    #pragma unroll
    for (int i = 0; i < 4; ++i) {
        float2 r = unpack2(acc[i]);
        r.x = fmaxf(r.x + bv.x, 0.f);
        r.y = fmaxf(r.y + bv.y, 0.f);
        int v = vb + ty * 4 + i;
        *(float2*)(out + v * COUT + tx * 2) = r;
    }
}

// ---------------- transposed 2x2x2 conv: t[m] = relu(x3[parent[m]] @ Wt[off[m]] + bt) ----------------
// Warp per fine voxel; W_t (128KB) served from L1.
__global__ void __launch_bounds__(256)
tconv_kernel(const float* __restrict__ x3, const int* __restrict__ parent,
             const int* __restrict__ offs, const float* __restrict__ Wt,
             const float* __restrict__ bt, float* __restrict__ tout) {
    __shared__ float sg[8][64];
    const int lane = threadIdx.x & 31;
    const int wid  = threadIdx.x >> 5;
    const int m = blockIdx.x * 8 + wid;   // 50000 blocks exactly covers M

    int p   = parent[m];
    int off = offs[m];
    float2 gv = make_float2(0.f, 0.f);
    if (p < N_COARSE) gv = *(const float2*)(x3 + p * 64 + lane * 2);
    *(float2*)(&sg[wid][lane * 2]) = gv;
    __syncwarp();

    const float* Wo = Wt + off * 4096;
    unsigned long long acc = 0ull;
    #pragma unroll
    for (int c = 0; c < 64; c += 4) {
        float4 g4 = *(const float4*)(&sg[wid][c]);
        float gs[4] = {g4.x, g4.y, g4.z, g4.w};
        #pragma unroll
        for (int cc = 0; cc < 4; ++cc) {
            float2 w = __ldg((const float2*)(Wo + (c + cc) * 64 + lane * 2));
            acc = ffma2(pack2(gs[cc], gs[cc]), pack2(w.x, w.y), acc);
        }
    }
    float2 bv = *(const float2*)(bt + lane * 2);
    float2 r = unpack2(acc);
    r.x = fmaxf(r.x + bv.x, 0.f);
    r.y = fmaxf(r.y + bv.y, 0.f);
    *(float2*)(tout + m * 64 + lane * 2) = r;
}

// ---------------- dense decoder: out = (relu(t @ Wd1 + bd1) @ Wd2 + bd2) + xup ----------------
// Persistent grid-stride over 32-voxel tiles; all weights in smem.
__global__ void __launch_bounds__(256)
dense_kernel(const float* __restrict__ t, const float* __restrict__ xup,
             const float* __restrict__ Wd1, const float* __restrict__ bd1,
             const float* __restrict__ Wd2, const float* __restrict__ bd2,
             float* __restrict__ out, int ntiles) {
    constexpr int V = 32;
    __shared__ float sW1[64 * 64];
    __shared__ float sW2[64 * 32];
    __shared__ float sb1[64];
    __shared__ float sb2[32];
    __shared__ float sx[V * 64];
    __shared__ float sy[V * 64];

    const int tid = threadIdx.x;
    const int tx  = tid & 31;
    const int ty  = tid >> 5;

    // one-time weight/bias load
    #pragma unroll
    for (int it = 0; it < 4; ++it) {
        int i = it * 1024 + tid * 4;
        *(float4*)(sW1 + i) = *(const float4*)(Wd1 + i);
    }
    #pragma unroll
    for (int it = 0; it < 2; ++it) {
        int i = it * 1024 + tid * 4;
        *(float4*)(sW2 + i) = *(const float4*)(Wd2 + i);
    }
    if (tid < 64) sb1[tid] = bd1[tid];
    if (tid < 32) sb2[tid] = bd2[tid];

    for (int tile = blockIdx.x; tile < ntiles; tile += gridDim.x) {
        const int vb = tile * V;
        __syncthreads();
        #pragma unroll
        for (int it = 0; it < 2; ++it) {
            int i = it * 1024 + tid * 4;
            *(float4*)(sx + i) = *(const float4*)(t + vb * 64 + i);
        }
        __syncthreads();

        // stage A: y = relu(sx @ Wd1 + bd1) -> sy
        unsigned long long acc[4] = {0ull, 0ull, 0ull, 0ull};
        #pragma unroll
        for (int c = 0; c < 64; c += 4) {
            float xs[4][4];
            #pragma unroll
            for (int i = 0; i < 4; ++i) {
                float4 t4 = *(const float4*)(sx + (ty * 4 + i) * 64 + c);
                xs[i][0] = t4.x; xs[i][1] = t4.y; xs[i][2] = t4.z; xs[i][3] = t4.w;
            }
            #pragma unroll
            for (int cc = 0; cc < 4; ++cc) {
                float2 w = *(const float2*)(sW1 + (c + cc) * 64 + tx * 2);
                unsigned long long w2 = pack2(w.x, w.y);
                #pragma unroll
                for (int i = 0; i < 4; ++i)
                    acc[i] = ffma2(pack2(xs[i][cc], xs[i][cc]), w2, acc[i]);
            }
        }
        float2 b1v = *(const float2*)(sb1 + tx * 2);
        #pragma unroll
        for (int i = 0; i < 4; ++i) {
            float2 r = unpack2(acc[i]);
            r.x = fmaxf(r.x + b1v.x, 0.f);
            r.y = fmaxf(r.y + b1v.y, 0.f);
            *(float2*)(sy + (ty * 4 + i) * 64 + tx * 2) = r;
        }
        __syncthreads();

        // stage B: z = sy @ Wd2 + bd2; out = z + xup  (voxel-pair packed)
        unsigned long long a01 = 0ull, a23 = 0ull;
        #pragma unroll
        for (int c = 0; c < 64; c += 4) {
            float ys[4][4];
            #pragma unroll
            for (int i = 0; i < 4; ++i) {
                float4 t4 = *(const float4*)(sy + (ty * 4 + i) * 64 + c);
                ys[i][0] = t4.x; ys[i][1] = t4.y; ys[i][2] = t4.z; ys[i][3] = t4.w;
            }
            #pragma unroll
            for (int cc = 0; cc < 4; ++cc) {
                float w = sW2[(c + cc) * 32 + tx];
                unsigned long long w2 = pack2(w, w);
                a01 = ffma2(pack2(ys[0][cc], ys[1][cc]), w2, a01);
                a23 = ffma2(pack2(ys[2][cc], ys[3][cc]), w2, a23);
            }
        }
        float b2v = sb2[tx];
        float2 z01 = unpack2(a01);
        float2 z23 = unpack2(a23);
        int m0 = vb + ty * 4;
        out[(m0 + 0) * 32 + tx] = z01.x + b2v + xup[(m0 + 0) * 32 + tx];
        out[(m0 + 1) * 32 + tx] = z01.y + b2v + xup[(m0 + 1) * 32 + tx];
        out[(m0 + 2) * 32 + tx] = z23.x + b2v + xup[(m0 + 2) * 32 + tx];
        out[(m0 + 3) * 32 + tx] = z23.y + b2v + xup[(m0 + 3) * 32 + tx];
    }
}

// ---------------- launch ----------------
extern "C" void kernel_launch(void* const* d_in, const int* in_sizes, int n_in,
                              void* d_out, int out_size) {
    const float* feats  = (const float*)d_in[0];   // [N,32]
    const float* xup    = (const float*)d_in[1];   // [M,32]
    const int*   nbr    = (const int*)d_in[2];     // [N,27]
    const int*   parent = (const int*)d_in[3];     // [M]
    const int*   offs   = (const int*)d_in[4];     // [M]
    const float* We1 = (const float*)d_in[5];
    const float* be1 = (const float*)d_in[6];
    const float* We2 = (const float*)d_in[7];
    const float* be2 = (const float*)d_in[8];
    const float* We3 = (const float*)d_in[9];
    const float* be3 = (const float*)d_in[10];
    const float* Wt  = (const float*)d_in[11];
    const float* bt  = (const float*)d_in[12];
    const float* Wd1 = (const float*)d_in[13];
    const float* bd1 = (const float*)d_in[14];
    const float* Wd2 = (const float*)d_in[15];
    const float* bd2 = (const float*)d_in[16];
    float* out = (float*)d_out;

    float *pA, *pB, *pT;
    cudaGetSymbolAddress((void**)&pA, g_bufA);
    cudaGetSymbolAddress((void**)&pB, g_bufB);
    cudaGetSymbolAddress((void**)&pT, g_t);

    conv3_kernel<C_IN> <<<N_COARSE / 32, 256>>>(feats, nbr, We1, be1, pA);
    conv3_kernel<C_HID><<<N_COARSE / 32, 256>>>(pA,    nbr, We2, be2, pB);
    conv3_kernel<C_HID><<<N_COARSE / 32, 256>>>(pB,    nbr, We3, be3, pA);
    tconv_kernel<<<M_FINE / 8, 256>>>(pA, parent, offs, Wt, bt, pT);
    dense_kernel<<<592, 256>>>(pT, xup, Wd1, bd1, Wd2, bd2, out, M_FINE / 32);
}